// round 9
// baseline (speedup 1.0000x reference)
#include <cuda_runtime.h>
#include <cstdint>

#define NBATCH 2
#define WW 80
#define NTOK 6400
#define NHEADS 8
#define HD 16
#define ATTN_SCALE 0.25f
#define QK_SCALE (0.25f * 1.4426950408889634f)   // fold softmax scale * log2(e) into Q

// ---------------- scratch (static __device__ — no allocations) ----------------
__device__ float g_Q[(size_t)NBATCH * NHEADS * NTOK * HD];     // (b,h,tok,d)
__device__ float g_K[(size_t)NBATCH * NHEADS * NTOK * HD];
__device__ float g_V[(size_t)NBATCH * NHEADS * NTOK * HD];
__device__ float g_Osum[(size_t)NBATCH * NTOK * 128];          // p4 output
__device__ float g_O8[(size_t)NBATCH * NTOK * 128];            // p8 output
__device__ float g_O40[(size_t)NBATCH * NTOK * 128];           // p40 output
__device__ float g_Wc[128 * 128];                              // wproj @ wfinal
__device__ float g_bc[128];                                    // 3*bproj@wfinal + bfinal

__device__ __forceinline__ void load16(const float* __restrict__ p, float* r) {
#pragma unroll
    for (int i = 0; i < 4; i++) {
        float4 t = ((const float4*)p)[i];
        r[4 * i + 0] = t.x; r[4 * i + 1] = t.y; r[4 * i + 2] = t.z; r[4 * i + 3] = t.w;
    }
}

__device__ __forceinline__ uint32_t bf16x2(float lo, float hi) {
    uint32_t r;
    asm("cvt.rn.bf16x2.f32 %0, %1, %2;" : "=r"(r) : "f"(hi), "f"(lo));
    return r;
}
__device__ __forceinline__ float ex2f(float x) {
    float r; asm("ex2.approx.f32 %0, %1;" : "=f"(r) : "f"(x)); return r;
}
__device__ __forceinline__ void mma_bf16(
    float& c0, float& c1, float& c2, float& c3,
    uint32_t a0, uint32_t a1, uint32_t a2, uint32_t a3,
    uint32_t b0, uint32_t b1) {
    asm("mma.sync.aligned.m16n8k16.row.col.f32.bf16.bf16.f32 "
        "{%0,%1,%2,%3}, {%4,%5,%6,%7}, {%8,%9}, {%0,%1,%2,%3};"
        : "+f"(c0), "+f"(c1), "+f"(c2), "+f"(c3)
        : "r"(a0), "r"(a1), "r"(a2), "r"(a3), "r"(b0), "r"(b1));
}
__device__ __forceinline__ void split_pair(float a0, float a1, uint32_t& hi, uint32_t& lo) {
    hi = bf16x2(a0, a1);
    float h0 = __uint_as_float(hi << 16);
    float h1 = __uint_as_float(hi & 0xffff0000u);
    lo = bf16x2(a0 - h0, a1 - h1);
}

// ---------------- QKV projection via bf16x3 mma: X(12800,128) @ [wq|wkv](128,384) ----------------
__global__ __launch_bounds__(256) void qkv_mma_kernel(
    const float* __restrict__ X, const float* __restrict__ wq,
    const float* __restrict__ wkv) {
    __shared__ uint32_t AsH[128][9], AsL[128][9];
    __shared__ uint32_t BsH[64][9], BsL[64][9];
    const int m0 = blockIdx.x * 128;
    const int n0 = blockIdx.y * 64;
    const float* bsrc; int ld;
    if (n0 < 128) { bsrc = wq + n0; ld = 128; }
    else          { bsrc = wkv + (n0 - 128); ld = 256; }
    const int tid = threadIdx.x;
    const int wid = tid >> 5, lane = tid & 31;
    const int lr = lane >> 2, lc = lane & 3;
    float c[8][4];
#pragma unroll
    for (int j = 0; j < 8; j++)
#pragma unroll
        for (int i = 0; i < 4; i++) c[j][i] = 0.f;

    for (int kc = 0; kc < 8; kc++) {
        __syncthreads();
        {
            int row = tid >> 1, hf = tid & 1;
            const float* src = &X[(size_t)(m0 + row) * 128 + kc * 16 + hf * 8];
            float4 f0 = *(const float4*)src;
            float4 f1 = *(const float4*)(src + 4);
            uint32_t h, l;
            split_pair(f0.x, f0.y, h, l); AsH[row][hf * 4 + 0] = h; AsL[row][hf * 4 + 0] = l;
            split_pair(f0.z, f0.w, h, l); AsH[row][hf * 4 + 1] = h; AsL[row][hf * 4 + 1] = l;
            split_pair(f1.x, f1.y, h, l); AsH[row][hf * 4 + 2] = h; AsL[row][hf * 4 + 2] = l;
            split_pair(f1.z, f1.w, h, l); AsH[row][hf * 4 + 3] = h; AsL[row][hf * 4 + 3] = l;
        }
#pragma unroll
        for (int ee = 0; ee < 2; ee++) {
            int e = tid + ee * 256;
            int n = e & 63, kp = e >> 6;
            float b0 = bsrc[(size_t)(kc * 16 + 2 * kp) * ld + n];
            float b1 = bsrc[(size_t)(kc * 16 + 2 * kp + 1) * ld + n];
            uint32_t h, l; split_pair(b0, b1, h, l);
            BsH[n][kp] = h; BsL[n][kp] = l;
        }
        __syncthreads();
        const int rbase = wid * 16;
        uint32_t aH0 = AsH[rbase + lr][lc],     aH1 = AsH[rbase + lr + 8][lc];
        uint32_t aH2 = AsH[rbase + lr][lc + 4], aH3 = AsH[rbase + lr + 8][lc + 4];
        uint32_t aL0 = AsL[rbase + lr][lc],     aL1 = AsL[rbase + lr + 8][lc];
        uint32_t aL2 = AsL[rbase + lr][lc + 4], aL3 = AsL[rbase + lr + 8][lc + 4];
#pragma unroll
        for (int j = 0; j < 8; j++) {
            uint32_t bH0 = BsH[8 * j + lr][lc], bH1 = BsH[8 * j + lr][lc + 4];
            uint32_t bL0 = BsL[8 * j + lr][lc], bL1 = BsL[8 * j + lr][lc + 4];
            mma_bf16(c[j][0], c[j][1], c[j][2], c[j][3], aH0, aH1, aH2, aH3, bH0, bH1);
            mma_bf16(c[j][0], c[j][1], c[j][2], c[j][3], aL0, aL1, aL2, aL3, bH0, bH1);
            mma_bf16(c[j][0], c[j][1], c[j][2], c[j][3], aH0, aH1, aH2, aH3, bL0, bL1);
        }
    }
    const int region = n0 >> 7;
    float* dst = (region == 0) ? g_Q : (region == 1 ? g_K : g_V);
#pragma unroll
    for (int j = 0; j < 8; j++) {
        int jb = (n0 & 127) + 8 * j + 2 * lc;
        int h = jb >> 4, dd = jb & 15;
        int t0 = m0 + wid * 16 + lr;
        int b0i = t0 / NTOK, tok0 = t0 - b0i * NTOK;
        *(float2*)&dst[((size_t)(b0i * NHEADS + h) * NTOK + tok0) * HD + dd] =
            make_float2(c[j][0], c[j][1]);
        int t1 = t0 + 8;
        int b1i = t1 / NTOK, tok1 = t1 - b1i * NTOK;
        *(float2*)&dst[((size_t)(b1i * NHEADS + h) * NTOK + tok1) * HD + dd] =
            make_float2(c[j][2], c[j][3]);
    }
}

// ---------------- fused attention (p40 mma + p8 + p4 + wc) ----------------
// grid 1568 x 320 threads:
//   [0,640)     p40 : bh = cta/10, qc = cta%10 (R7-validated mma body, inline Vc/Vr)
//   [640,1040)  p8  : 400 CTAs, each (b, blk, 4-head group); 256 active compute threads
//   [1040,1440) p4  : 400 CTAs, each (b, 2 blocks, 8 heads); 256 active compute threads
//   [1440,1568) wc  : Wc = wproj@wfinal row per CTA; bc
union SmemU {
    struct {
        uint32_t KsU[512];
        uint32_t VtU[16 * 36];
        float Os[160][17];
        float rw[79 * 16], rh[79 * 16];
        float Vc[40][16], Vr[40][16];
    } p40;
    struct {
        float Ks[4][64][16], Vs[4][64][16];
        float Vc[4][8][16], Vr[4][8][16];
        float rwT[16][16], rhT[16][16];   // [d][idx], idx < 15
    } p8;
    struct {
        float Ks[2][8][16][16], Vs[2][8][16][16];
        float Vc[2][8][4][16], Vr[2][8][4][16];
        float rwT[16][8], rhT[16][8];     // [d][idx], idx < 7
    } p4;
};

__global__ __launch_bounds__(320) void fused_attn_kernel(
    const float* __restrict__ rw0, const float* __restrict__ rh0,
    const float* __restrict__ rw1, const float* __restrict__ rh1,
    const float* __restrict__ rw2, const float* __restrict__ rh2,
    const float* __restrict__ wproj, const float* __restrict__ wfinal,
    const float* __restrict__ bproj, const float* __restrict__ bfinal) {
    __shared__ __align__(16) SmemU s;
    const int cta = blockIdx.x;
    const int tid = threadIdx.x;

    if (cta < 640) {
        // ================= p40 role (R7-validated bf16 mma flash attention) ==========
        const int bh = cta / 10;
        const int qc = cta - bh * 10;
        const int b = bh >> 5, blk = (bh >> 3) & 3, h = bh & 7;
        const int bi = blk >> 1, bj = blk & 1;
        const size_t base = (size_t)(b * NHEADS + h) * NTOK;

        for (int e = tid; e < 79 * 16; e += 320) { s.p40.rw[e] = rw2[e]; s.p40.rh[e] = rh2[e]; }
        // inline Vc/Vr (same summation order as the old vsum40_kernel)
        {
            const float* Vb = g_V + base * HD;
            for (int e = tid; e < 640; e += 320) {
                int idx = e >> 4, dd = e & 15;
                float sc = 0.f, sr = 0.f;
                for (int k2 = 0; k2 < 40; k2++) {
                    sc += Vb[((bi * 40 + k2) * WW + bj * 40 + idx) * HD + dd];
                    sr += Vb[((bi * 40 + idx) * WW + bj * 40 + k2) * HD + dd];
                }
                s.p40.Vc[idx][dd] = sc;
                s.p40.Vr[idx][dd] = sr;
            }
        }

        const int wid = tid >> 5, lane = tid & 31;
        const int lr = lane >> 2, lc = lane & 3;
        uint32_t qa0, qa1, qa2, qa3;
        {
            int qia = qc * 160 + wid * 16 + lr;
            int qib = qia + 8;
            int ra = qia / 40, ca = qia - ra * 40;
            int rb = qib / 40, cb = qib - rb * 40;
            const float* qpa = &g_Q[(base + (bi * 40 + ra) * WW + bj * 40 + ca) * HD];
            const float* qpb = &g_Q[(base + (bi * 40 + rb) * WW + bj * 40 + cb) * HD];
            float2 f;
            f = *(const float2*)&qpa[2 * lc];     qa0 = bf16x2(f.x * QK_SCALE, f.y * QK_SCALE);
            f = *(const float2*)&qpb[2 * lc];     qa1 = bf16x2(f.x * QK_SCALE, f.y * QK_SCALE);
            f = *(const float2*)&qpa[2 * lc + 8]; qa2 = bf16x2(f.x * QK_SCALE, f.y * QK_SCALE);
            f = *(const float2*)&qpb[2 * lc + 8]; qa3 = bf16x2(f.x * QK_SCALE, f.y * QK_SCALE);
        }
        float oc0[4] = {0.f, 0.f, 0.f, 0.f};
        float oc1[4] = {0.f, 0.f, 0.f, 0.f};
        float rsum0 = 0.f, rsum1 = 0.f;

        for (int t = 0; t < 25; t++) {
            __syncthreads();
            for (int e = tid; e < 512; e += 320) {
                int key = e >> 3, dp = e & 7;
                int kidx = t * 64 + key;
                int kr = kidx / 40, kc2 = kidx - kr * 40;
                float2 f = *(const float2*)&g_K[(base + (bi * 40 + kr) * WW + bj * 40 + kc2) * HD + 2 * dp];
                s.p40.KsU[e] = bf16x2(f.x, f.y);
            }
            for (int e = tid; e < 512; e += 320) {
                int d = e >> 5, k2 = e & 31;
                int kidx = t * 64 + 2 * k2;
                int kr = kidx / 40, kc2 = kidx - kr * 40;
                size_t tok = base + (bi * 40 + kr) * WW + bj * 40 + kc2;
                float lo = g_V[tok * HD + d];
                float hi = g_V[(tok + 1) * HD + d];
                s.p40.VtU[d * 36 + k2] = bf16x2(lo, hi);
            }
            __syncthreads();

            uint32_t p[8][2];
#pragma unroll
            for (int g = 0; g < 8; g++) {
                float c0 = 0.f, c1 = 0.f, c2 = 0.f, c3 = 0.f;
                uint32_t kb0 = s.p40.KsU[(8 * g + lr) * 8 + lc];
                uint32_t kb1 = s.p40.KsU[(8 * g + lr) * 8 + lc + 4];
                mma_bf16(c0, c1, c2, c3, qa0, qa1, qa2, qa3, kb0, kb1);
                float e0 = ex2f(c0), e1 = ex2f(c1), e2 = ex2f(c2), e3 = ex2f(c3);
                rsum0 += e0 + e1;
                rsum1 += e2 + e3;
                p[g][0] = bf16x2(e0, e1);
                p[g][1] = bf16x2(e2, e3);
            }
#pragma unroll
            for (int gp = 0; gp < 4; gp++) {
                uint32_t a0 = p[2 * gp][0], a1 = p[2 * gp][1];
                uint32_t a2 = p[2 * gp + 1][0], a3 = p[2 * gp + 1][1];
                uint32_t vb0 = s.p40.VtU[lr * 36 + 8 * gp + lc];
                uint32_t vb1 = s.p40.VtU[lr * 36 + 8 * gp + lc + 4];
                mma_bf16(oc0[0], oc0[1], oc0[2], oc0[3], a0, a1, a2, a3, vb0, vb1);
                vb0 = s.p40.VtU[(8 + lr) * 36 + 8 * gp + lc];
                vb1 = s.p40.VtU[(8 + lr) * 36 + 8 * gp + lc + 4];
                mma_bf16(oc1[0], oc1[1], oc1[2], oc1[3], a0, a1, a2, a3, vb0, vb1);
            }
        }
        rsum0 += __shfl_xor_sync(0xffffffffu, rsum0, 1);
        rsum0 += __shfl_xor_sync(0xffffffffu, rsum0, 2);
        rsum1 += __shfl_xor_sync(0xffffffffu, rsum1, 1);
        rsum1 += __shfl_xor_sync(0xffffffffu, rsum1, 2);
        float inv0 = 1.f / rsum0, inv1 = 1.f / rsum1;
        {
            int ql = wid * 16;
            s.p40.Os[ql + lr][2 * lc]         = oc0[0] * inv0;
            s.p40.Os[ql + lr][2 * lc + 1]     = oc0[1] * inv0;
            s.p40.Os[ql + lr + 8][2 * lc]     = oc0[2] * inv1;
            s.p40.Os[ql + lr + 8][2 * lc + 1] = oc0[3] * inv1;
            s.p40.Os[ql + lr][2 * lc + 8]     = oc1[0] * inv0;
            s.p40.Os[ql + lr][2 * lc + 9]     = oc1[1] * inv0;
            s.p40.Os[ql + lr + 8][2 * lc + 8] = oc1[2] * inv1;
            s.p40.Os[ql + lr + 8][2 * lc + 9] = oc1[3] * inv1;
        }
        __syncthreads();

        const int qloc = tid >> 1, half = tid & 1;
        const int qi = qc * 160 + qloc;
        const int r = qi / 40, c = qi - r * 40;
        float q[16];
        load16(&g_Q[(base + (bi * 40 + r) * WW + bj * 40 + c) * HD], q);
        float o[8] = {0.f, 0.f, 0.f, 0.f, 0.f, 0.f, 0.f, 0.f};
        const int off = half ? (39 - r) : (39 - c);
        const float* tbl = half ? s.p40.rh : s.p40.rw;
#pragma unroll 2
        for (int kc = 0; kc < 40; kc++) {
            const float* tp = &tbl[(kc + off) * 16];
            float mine = 0.f;
#pragma unroll
            for (int d = 0; d < 16; d++) mine = fmaf(q[d], tp[d], mine);
            float other = __shfl_xor_sync(0xffffffffu, mine, 1);
            float w  = half ? other : mine;
            float wh = half ? mine  : other;
#pragma unroll
            for (int j = 0; j < 8; j++)
                o[j] = fmaf(w, s.p40.Vc[kc][half * 8 + j], fmaf(wh, s.p40.Vr[kc][half * 8 + j], o[j]));
        }
        const int pbase = (bi * 2 + bj) * 1600;
        float* dst = &g_O40[((size_t)b * NTOK + pbase + qi) * 128 + h * HD + half * 8];
#pragma unroll
        for (int j4 = 0; j4 < 2; j4++) {
            float4 val = make_float4(
                o[4 * j4 + 0] + s.p40.Os[qloc][half * 8 + 4 * j4 + 0],
                o[4 * j4 + 1] + s.p40.Os[qloc][half * 8 + 4 * j4 + 1],
                o[4 * j4 + 2] + s.p40.Os[qloc][half * 8 + 4 * j4 + 2],
                o[4 * j4 + 3] + s.p40.Os[qloc][half * 8 + 4 * j4 + 3]);
            *(float4*)&dst[4 * j4] = val;
        }
    } else if (cta < 1040) {
        // ================= p8 role: (b, blk, head-group of 4), 64 keys ==============
        const int cta2 = cta - 640;
        const int sub = cta2 & 1;
        const int tmp = cta2 >> 1;           // b*100 + blk
        const int blk = tmp % 100;
        const int b = tmp / 100;
        const int bi = blk / 10, bj = blk % 10;

        for (int e = tid; e < 15 * 16; e += 320) {
            int rr = e >> 4, d = e & 15;
            s.p8.rwT[d][rr] = rw1[e];
            s.p8.rhT[d][rr] = rh1[e];
        }
        for (int e = tid; e < 1024; e += 320) {
            int hl = e >> 8;
            int rem = e & 255;
            int key = rem >> 2, part = (rem & 3) << 2;
            int kr = key >> 3, kc = key & 7;
            int ktok = (bi * 8 + kr) * WW + bj * 8 + kc;
            size_t basek = (size_t)(b * NHEADS + sub * 4 + hl) * NTOK;
            *(float4*)&s.p8.Ks[hl][key][part] = *(const float4*)&g_K[(basek + ktok) * HD + part];
            *(float4*)&s.p8.Vs[hl][key][part] = *(const float4*)&g_V[(basek + ktok) * HD + part];
        }
        __syncthreads();
        for (int e = tid; e < 512; e += 320) {
            int hl = e >> 7;
            int rem = e & 127;
            int idx = rem >> 4, dd = rem & 15;
            float sc = 0.f, sr = 0.f;
#pragma unroll
            for (int k2 = 0; k2 < 8; k2++) {
                sc += s.p8.Vs[hl][k2 * 8 + idx][dd];
                sr += s.p8.Vs[hl][idx * 8 + k2][dd];
            }
            s.p8.Vc[hl][idx][dd] = sc;
            s.p8.Vr[hl][idx][dd] = sr;
        }
        __syncthreads();

        if (tid < 256) {
            const int hh = tid >> 6;
            const int qi = tid & 63;
            const int h = sub * 4 + hh;
            const int r = qi >> 3, c = qi & 7;
            const int qtok = (bi * 8 + r) * WW + bj * 8 + c;
            const size_t base = (size_t)(b * NHEADS + h) * NTOK;
            float q[16];
            load16(&g_Q[(base + qtok) * HD], q);
            float o[16];
#pragma unroll
            for (int d = 0; d < 16; d++) o[d] = 0.f;
            float ssum = 0.f;
            for (int kk = 0; kk < 64; kk++) {
                float kv[16];
                load16(&s.p8.Ks[hh][kk][0], kv);
                float ss = 0.f;
#pragma unroll
                for (int d = 0; d < 16; d++) ss = fmaf(q[d], kv[d], ss);
                float ew = __expf(ss * ATTN_SCALE);
                ssum += ew;
                float vv[16];
                load16(&s.p8.Vs[hh][kk][0], vv);
#pragma unroll
                for (int d = 0; d < 16; d++) o[d] = fmaf(ew, vv[d], o[d]);
            }
            float inv = 1.f / ssum;
#pragma unroll
            for (int d = 0; d < 16; d++) o[d] *= inv;

            const int cw = 7 - c, rw = 7 - r;
#pragma unroll 2
            for (int kc = 0; kc < 8; kc++) {
                float w = 0.f, wh = 0.f;
#pragma unroll
                for (int d = 0; d < 16; d++) {
                    w = fmaf(q[d], s.p8.rwT[d][kc + cw], w);
                    wh = fmaf(q[d], s.p8.rhT[d][kc + rw], wh);
                }
                float vcv[16], vrv[16];
                load16(&s.p8.Vc[hh][kc][0], vcv);
                load16(&s.p8.Vr[hh][kc][0], vrv);
#pragma unroll
                for (int d = 0; d < 16; d++) {
                    o[d] = fmaf(w, vcv[d], o[d]);
                    o[d] = fmaf(wh, vrv[d], o[d]);
                }
            }
            const int dtok = (bi * 10 + bj) * 64 + qi;
            float* dst = g_O8 + ((size_t)b * NTOK + dtok) * 128 + h * HD;
#pragma unroll
            for (int d4 = 0; d4 < 4; d4++)
                *(float4*)&dst[4 * d4] =
                    make_float4(o[4 * d4], o[4 * d4 + 1], o[4 * d4 + 2], o[4 * d4 + 3]);
        }
    } else if (cta < 1440) {
        // ================= p4 role: (b, 2 spatial blocks, 8 heads), 16 keys ==========
        const int cta3 = cta - 1040;
        const int u = cta3 % 200;
        const int b = cta3 / 200;

        for (int e = tid; e < 7 * 16; e += 320) {
            int rr = e >> 4, d = e & 15;
            s.p4.rwT[d][rr] = rw0[e];
            s.p4.rhT[d][rr] = rh0[e];
        }
        for (int e = tid; e < 1024; e += 320) {
            int g = e >> 9;
            int rem = e & 511;
            int h = rem >> 6;
            int rem2 = rem & 63;
            int key = rem2 >> 2, part = (rem2 & 3) << 2;
            int gblk = 2 * u + g;
            int bi = gblk / 20, bj = gblk % 20;
            int kr = key >> 2, kc = key & 3;
            int ktok = (bi * 4 + kr) * WW + bj * 4 + kc;
            size_t basek = (size_t)(b * NHEADS + h) * NTOK;
            *(float4*)&s.p4.Ks[g][h][key][part] = *(const float4*)&g_K[(basek + ktok) * HD + part];
            *(float4*)&s.p4.Vs[g][h][key][part] = *(const float4*)&g_V[(basek + ktok) * HD + part];
        }
        __syncthreads();
        for (int e = tid; e < 1024; e += 320) {
            int g = e >> 9;
            int rem = e & 511;
            int h = rem >> 6;
            int rem2 = rem & 63;
            int idx = rem2 >> 4, dd = rem2 & 15;
            float sc = 0.f, sr = 0.f;
#pragma unroll
            for (int k2 = 0; k2 < 4; k2++) {
                sc += s.p4.Vs[g][h][k2 * 4 + idx][dd];
                sr += s.p4.Vs[g][h][idx * 4 + k2][dd];
            }
            s.p4.Vc[g][h][idx][dd] = sc;
            s.p4.Vr[g][h][idx][dd] = sr;
        }
        __syncthreads();

        if (tid < 256) {
            const int g = tid >> 7;
            const int h = (tid >> 4) & 7;
            const int qi = tid & 15;
            const int gblk = 2 * u + g;
            const int bi = gblk / 20, bj = gblk % 20;
            const int r = qi >> 2, c = qi & 3;
            const int qtok = (bi * 4 + r) * WW + bj * 4 + c;
            const size_t base = (size_t)(b * NHEADS + h) * NTOK;
            float q[16];
            load16(&g_Q[(base + qtok) * HD], q);
            float o[16];
#pragma unroll
            for (int d = 0; d < 16; d++) o[d] = 0.f;
            float ssum = 0.f;
            for (int kk = 0; kk < 16; kk++) {
                float kv[16];
                load16(&s.p4.Ks[g][h][kk][0], kv);
                float ss = 0.f;
#pragma unroll
                for (int d = 0; d < 16; d++) ss = fmaf(q[d], kv[d], ss);
                float ew = __expf(ss * ATTN_SCALE);
                ssum += ew;
                float vv[16];
                load16(&s.p4.Vs[g][h][kk][0], vv);
#pragma unroll
                for (int d = 0; d < 16; d++) o[d] = fmaf(ew, vv[d], o[d]);
            }
            float inv = 1.f / ssum;
#pragma unroll
            for (int d = 0; d < 16; d++) o[d] *= inv;

            const int cw = 3 - c, rw = 3 - r;
#pragma unroll
            for (int kc = 0; kc < 4; kc++) {
                float w = 0.f, wh = 0.f;
#pragma unroll
                for (int d = 0; d < 16; d++) {
                    w = fmaf(q[d], s.p4.rwT[d][kc + cw], w);
                    wh = fmaf(q[d], s.p4.rhT[d][kc + rw], wh);
                }
                float vcv[16], vrv[16];
                load16(&s.p4.Vc[g][h][kc][0], vcv);
                load16(&s.p4.Vr[g][h][kc][0], vrv);
#pragma unroll
                for (int d = 0; d < 16; d++) {
                    o[d] = fmaf(w, vcv[d], o[d]);
                    o[d] = fmaf(wh, vrv[d], o[d]);
                }
            }
            const int dtok = gblk * 16 + qi;
            float* dst = g_Osum + ((size_t)b * NTOK + dtok) * 128 + h * HD;
#pragma unroll
            for (int d4 = 0; d4 < 4; d4++)
                *(float4*)&dst[4 * d4] =
                    make_float4(o[4 * d4], o[4 * d4 + 1], o[4 * d4 + 2], o[4 * d4 + 3]);
        }
    } else {
        // ================= wc role: Wc = wproj @ wfinal ; bc ==========================
        const int i = cta - 1440;
        if (tid < 128) {
            const int j = tid;
            float sv = 0.f;
            for (int k = 0; k < 128; k++) sv = fmaf(wproj[i * 128 + k], wfinal[k * 128 + j], sv);
            g_Wc[i * 128 + j] = sv;
            if (i == 0) {
                float sb = 0.f;
                for (int k = 0; k < 128; k++) sb = fmaf(bproj[k], wfinal[k * 128 + j], sb);
                g_bc[j] = 3.f * sb + bfinal[j];
            }
        }
    }
}

// ---------------- final via bf16x3 mma: out = (O4+O8+O40)(12800,128) @ Wc + bc -----
__global__ __launch_bounds__(256) void final_mma_kernel(float* __restrict__ out) {
    __shared__ uint32_t AsH[128][9], AsL[128][9];
    __shared__ uint32_t BsH[64][9], BsL[64][9];
    const int m0 = blockIdx.x * 128;
    const int n0 = blockIdx.y * 64;
    const int tid = threadIdx.x;
    const int wid = tid >> 5, lane = tid & 31;
    const int lr = lane >> 2, lc = lane & 3;
    float c[8][4];
#pragma unroll
    for (int j = 0; j < 8; j++)
#pragma unroll
        for (int i = 0; i < 4; i++) c[j][i] = 0.f;

    for (int kc = 0; kc < 8; kc++) {
        __syncthreads();
        {
            int row = tid >> 1, hf = tid & 1;
            size_t off = (size_t)(m0 + row) * 128 + kc * 16 + hf * 8;
            float4 a0 = *(const float4*)&g_Osum[off];
            float4 a1 = *(const float4*)&g_Osum[off + 4];
            float4 b0 = *(const float4*)&g_O8[off];
            float4 b1 = *(const float4*)&g_O8[off + 4];
            float4 d0 = *(const float4*)&g_O40[off];
            float4 d1 = *(const float4*)&g_O40[off + 4];
            float4 f0 = make_float4(a0.x + b0.x + d0.x, a0.y + b0.y + d0.y,
                                    a0.z + b0.z + d0.z, a0.w + b0.w + d0.w);
            float4 f1 = make_float4(a1.x + b1.x + d1.x, a1.y + b1.y + d1.y,
                                    a1.z + b1.z + d1.z, a1.w + b1.w + d1.w);
            uint32_t h, l;
            split_pair(f0.x, f0.y, h, l); AsH[row][hf * 4 + 0] = h; AsL[row][hf * 4 + 0] = l;
            split_pair(f0.z, f0.w, h, l); AsH[row][hf * 4 + 1] = h; AsL[row][hf * 4 + 1] = l;
            split_pair(f1.x, f1.y, h, l); AsH[row][hf * 4 + 2] = h; AsL[row][hf * 4 + 2] = l;
            split_pair(f1.z, f1.w, h, l); AsH[row][hf * 4 + 3] = h; AsL[row][hf * 4 + 3] = l;
        }
#pragma unroll
        for (int ee = 0; ee < 2; ee++) {
            int e = tid + ee * 256;
            int n = e & 63, kp = e >> 6;
            float b0 = g_Wc[(size_t)(kc * 16 + 2 * kp) * 128 + n0 + n];
            float b1 = g_Wc[(size_t)(kc * 16 + 2 * kp + 1) * 128 + n0 + n];
            uint32_t h, l; split_pair(b0, b1, h, l);
            BsH[n][kp] = h; BsL[n][kp] = l;
        }
        __syncthreads();
        const int rbase = wid * 16;
        uint32_t aH0 = AsH[rbase + lr][lc],     aH1 = AsH[rbase + lr + 8][lc];
        uint32_t aH2 = AsH[rbase + lr][lc + 4], aH3 = AsH[rbase + lr + 8][lc + 4];
        uint32_t aL0 = AsL[rbase + lr][lc],     aL1 = AsL[rbase + lr + 8][lc];
        uint32_t aL2 = AsL[rbase + lr][lc + 4], aL3 = AsL[rbase + lr + 8][lc + 4];
#pragma unroll
        for (int j = 0; j < 8; j++) {
            uint32_t bH0 = BsH[8 * j + lr][lc], bH1 = BsH[8 * j + lr][lc + 4];
            uint32_t bL0 = BsL[8 * j + lr][lc], bL1 = BsL[8 * j + lr][lc + 4];
            mma_bf16(c[j][0], c[j][1], c[j][2], c[j][3], aH0, aH1, aH2, aH3, bH0, bH1);
            mma_bf16(c[j][0], c[j][1], c[j][2], c[j][3], aL0, aL1, aL2, aL3, bH0, bH1);
            mma_bf16(c[j][0], c[j][1], c[j][2], c[j][3], aH0, aH1, aH2, aH3, bL0, bL1);
        }
    }
#pragma unroll
    for (int j = 0; j < 8; j++) {
        int ncol = n0 + 8 * j + 2 * lc;
        float b0v = g_bc[ncol], b1v = g_bc[ncol + 1];
        int t0 = m0 + wid * 16 + lr;
        *(float2*)&out[(size_t)t0 * 128 + ncol] = make_float2(c[j][0] + b0v, c[j][1] + b1v);
        *(float2*)&out[(size_t)(t0 + 8) * 128 + ncol] = make_float2(c[j][2] + b0v, c[j][3] + b1v);
    }
}

// ---------------- launcher: 3 kernels ----------------
extern "C" void kernel_launch(void* const* d_in, const int* in_sizes, int n_in,
                              void* d_out, int out_size) {
    (void)in_sizes; (void)n_in; (void)out_size;
    const float* x      = (const float*)d_in[0];
    const float* wq     = (const float*)d_in[1];
    const float* wkv    = (const float*)d_in[2];
    const float* wproj  = (const float*)d_in[3];
    const float* bproj  = (const float*)d_in[4];
    const float* wfinal = (const float*)d_in[5];
    const float* bfinal = (const float*)d_in[6];
    const float* rw0 = (const float*)d_in[7];
    const float* rh0 = (const float*)d_in[8];
    const float* rw1 = (const float*)d_in[9];
    const float* rh1 = (const float*)d_in[10];
    const float* rw2 = (const float*)d_in[11];
    const float* rh2 = (const float*)d_in[12];
    float* out = (float*)d_out;

    qkv_mma_kernel<<<dim3(100, 6), 256>>>(x, wq, wkv);
    fused_attn_kernel<<<1568, 320>>>(rw0, rh0, rw1, rh1, rw2, rh2,
                                     wproj, wfinal, bproj, bfinal);
    final_mma_kernel<<<dim3(100, 2), 256>>>(out);
}

// round 11
// speedup vs baseline: 1.1930x; 1.1930x over previous
#include <cuda_runtime.h>
#include <cstdint>

#define NBATCH 2
#define WW 80
#define NTOK 6400
#define NHEADS 8
#define HD 16
#define ATTN_SCALE 0.25f
#define QK_SCALE (0.25f * 1.4426950408889634f)   // fold softmax scale * log2(e) into Q

// ---------------- scratch (static __device__ — no allocations) ----------------
__device__ float g_Q[(size_t)NBATCH * NHEADS * NTOK * HD];     // (b,h,tok,d)
__device__ float g_K[(size_t)NBATCH * NHEADS * NTOK * HD];
__device__ float g_V[(size_t)NBATCH * NHEADS * NTOK * HD];
__device__ float g_Osum[(size_t)NBATCH * NTOK * 128];          // (b,dest_tok, h*16+d)
__device__ float g_Wc[128 * 128];                              // wproj @ wfinal
__device__ float g_bc[128];                                    // 3*bproj@wfinal + bfinal
__device__ float g_Vc40[64 * 40 * 16];                         // per bh: column sums of V
__device__ float g_Vr40[64 * 40 * 16];                         // per bh: row sums of V
__device__ uint32_t g_Kp[(size_t)64 * 25 * 512];               // packed bf16x2 K tiles
__device__ uint32_t g_Vtp[(size_t)64 * 25 * 512];              // packed bf16x2 V^T tiles

__device__ __forceinline__ void load16(const float* __restrict__ p, float* r) {
#pragma unroll
    for (int i = 0; i < 4; i++) {
        float4 t = ((const float4*)p)[i];
        r[4 * i + 0] = t.x; r[4 * i + 1] = t.y; r[4 * i + 2] = t.z; r[4 * i + 3] = t.w;
    }
}

__device__ __forceinline__ uint32_t bf16x2(float lo, float hi) {
    uint32_t r;
    asm("cvt.rn.bf16x2.f32 %0, %1, %2;" : "=r"(r) : "f"(hi), "f"(lo));
    return r;
}
__device__ __forceinline__ float ex2f(float x) {
    float r; asm("ex2.approx.f32 %0, %1;" : "=f"(r) : "f"(x)); return r;
}
__device__ __forceinline__ void mma_bf16(
    float& c0, float& c1, float& c2, float& c3,
    uint32_t a0, uint32_t a1, uint32_t a2, uint32_t a3,
    uint32_t b0, uint32_t b1) {
    asm("mma.sync.aligned.m16n8k16.row.col.f32.bf16.bf16.f32 "
        "{%0,%1,%2,%3}, {%4,%5,%6,%7}, {%8,%9}, {%0,%1,%2,%3};"
        : "+f"(c0), "+f"(c1), "+f"(c2), "+f"(c3)
        : "r"(a0), "r"(a1), "r"(a2), "r"(a3), "r"(b0), "r"(b1));
}
__device__ __forceinline__ void split_pair(float a0, float a1, uint32_t& hi, uint32_t& lo) {
    hi = bf16x2(a0, a1);
    float h0 = __uint_as_float(hi << 16);
    float h1 = __uint_as_float(hi & 0xffff0000u);
    lo = bf16x2(a0 - h0, a1 - h1);
}

// ---------------- QKV projection via bf16x3 mma: X(12800,128) @ [wq|wkv](128,384) ----------------
__global__ __launch_bounds__(256) void qkv_mma_kernel(
    const float* __restrict__ X, const float* __restrict__ wq,
    const float* __restrict__ wkv) {
    __shared__ uint32_t AsH[128][9], AsL[128][9];
    __shared__ uint32_t BsH[64][9], BsL[64][9];
    const int m0 = blockIdx.x * 128;
    const int n0 = blockIdx.y * 64;
    const float* bsrc; int ld;
    if (n0 < 128) { bsrc = wq + n0; ld = 128; }
    else          { bsrc = wkv + (n0 - 128); ld = 256; }
    const int tid = threadIdx.x;
    const int wid = tid >> 5, lane = tid & 31;
    const int lr = lane >> 2, lc = lane & 3;
    float c[8][4];
#pragma unroll
    for (int j = 0; j < 8; j++)
#pragma unroll
        for (int i = 0; i < 4; i++) c[j][i] = 0.f;

    for (int kc = 0; kc < 8; kc++) {
        __syncthreads();
        {
            int row = tid >> 1, hf = tid & 1;
            const float* src = &X[(size_t)(m0 + row) * 128 + kc * 16 + hf * 8];
            float4 f0 = *(const float4*)src;
            float4 f1 = *(const float4*)(src + 4);
            uint32_t h, l;
            split_pair(f0.x, f0.y, h, l); AsH[row][hf * 4 + 0] = h; AsL[row][hf * 4 + 0] = l;
            split_pair(f0.z, f0.w, h, l); AsH[row][hf * 4 + 1] = h; AsL[row][hf * 4 + 1] = l;
            split_pair(f1.x, f1.y, h, l); AsH[row][hf * 4 + 2] = h; AsL[row][hf * 4 + 2] = l;
            split_pair(f1.z, f1.w, h, l); AsH[row][hf * 4 + 3] = h; AsL[row][hf * 4 + 3] = l;
        }
#pragma unroll
        for (int ee = 0; ee < 2; ee++) {
            int e = tid + ee * 256;
            int n = e & 63, kp = e >> 6;
            float b0 = bsrc[(size_t)(kc * 16 + 2 * kp) * ld + n];
            float b1 = bsrc[(size_t)(kc * 16 + 2 * kp + 1) * ld + n];
            uint32_t h, l; split_pair(b0, b1, h, l);
            BsH[n][kp] = h; BsL[n][kp] = l;
        }
        __syncthreads();
        const int rbase = wid * 16;
        uint32_t aH0 = AsH[rbase + lr][lc],     aH1 = AsH[rbase + lr + 8][lc];
        uint32_t aH2 = AsH[rbase + lr][lc + 4], aH3 = AsH[rbase + lr + 8][lc + 4];
        uint32_t aL0 = AsL[rbase + lr][lc],     aL1 = AsL[rbase + lr + 8][lc];
        uint32_t aL2 = AsL[rbase + lr][lc + 4], aL3 = AsL[rbase + lr + 8][lc + 4];
#pragma unroll
        for (int j = 0; j < 8; j++) {
            uint32_t bH0 = BsH[8 * j + lr][lc], bH1 = BsH[8 * j + lr][lc + 4];
            uint32_t bL0 = BsL[8 * j + lr][lc], bL1 = BsL[8 * j + lr][lc + 4];
            mma_bf16(c[j][0], c[j][1], c[j][2], c[j][3], aH0, aH1, aH2, aH3, bH0, bH1);
            mma_bf16(c[j][0], c[j][1], c[j][2], c[j][3], aL0, aL1, aL2, aL3, bH0, bH1);
            mma_bf16(c[j][0], c[j][1], c[j][2], c[j][3], aH0, aH1, aH2, aH3, bL0, bL1);
        }
    }
    const int region = n0 >> 7;
    float* dst = (region == 0) ? g_Q : (region == 1 ? g_K : g_V);
#pragma unroll
    for (int j = 0; j < 8; j++) {
        int jb = (n0 & 127) + 8 * j + 2 * lc;
        int h = jb >> 4, dd = jb & 15;
        int t0 = m0 + wid * 16 + lr;
        int b0i = t0 / NTOK, tok0 = t0 - b0i * NTOK;
        *(float2*)&dst[((size_t)(b0i * NHEADS + h) * NTOK + tok0) * HD + dd] =
            make_float2(c[j][0], c[j][1]);
        int t1 = t0 + 8;
        int b1i = t1 / NTOK, tok1 = t1 - b1i * NTOK;
        *(float2*)&dst[((size_t)(b1i * NHEADS + h) * NTOK + tok1) * HD + dd] =
            make_float2(c[j][2], c[j][3]);
    }
}

// ---------------- Wc = wproj @ wfinal ; bc ----------------
__global__ void wc_kernel(const float* __restrict__ wproj, const float* __restrict__ wfinal,
                          const float* __restrict__ bproj, const float* __restrict__ bfinal) {
    int i = blockIdx.x, j = threadIdx.x;
    float s = 0.f;
    for (int k = 0; k < 128; k++) s = fmaf(wproj[i * 128 + k], wfinal[k * 128 + j], s);
    g_Wc[i * 128 + j] = s;
    if (i == 0) {
        float sb = 0.f;
        for (int k = 0; k < 128; k++) sb = fmaf(bproj[k], wfinal[k * 128 + j], sb);
        g_bc[j] = 3.f * sb + bfinal[j];
    }
}

// ---------------- V row/col sums for p=40 rel-pos decomposition ----------------
__global__ void vsum40_kernel() {
    const int bh = blockIdx.x;
    const int b = bh >> 5, blk = (bh >> 3) & 3, h = bh & 7;
    const int bi = blk >> 1, bj = blk & 1;
    const int tid = threadIdx.x;                // 640
    const int idx = tid >> 4, dd = tid & 15;
    const float* Vb = g_V + (size_t)(b * NHEADS + h) * NTOK * HD;
    float sc = 0.f, sr = 0.f;
    for (int k2 = 0; k2 < 40; k2++) {
        sc += Vb[((bi * 40 + k2) * WW + bj * 40 + idx) * HD + dd];
        sr += Vb[((bi * 40 + idx) * WW + bj * 40 + k2) * HD + dd];
    }
    g_Vc40[bh * 640 + idx * 16 + dd] = sc;
    g_Vr40[bh * 640 + idx * 16 + dd] = sr;
}

// ---------------- pack K / V^T tiles to bf16x2 in attn40's exact smem layout ----------------
// grid 1600 (= bh*25 + t), 256 threads.
__global__ __launch_bounds__(256) void pack40_kernel() {
    const int idx = blockIdx.x;
    const int bh = idx / 25, t = idx - bh * 25;
    const int b = bh >> 5, blk = (bh >> 3) & 3, h = bh & 7;
    const int bi = blk >> 1, bj = blk & 1;
    const size_t base = (size_t)(b * NHEADS + h) * NTOK;
    const int tid = threadIdx.x;
    uint32_t* Kdst = &g_Kp[(size_t)idx * 512];
    uint32_t* Vdst = &g_Vtp[(size_t)idx * 512];
    for (int e = tid; e < 512; e += 256) {
        int key = e >> 3, dp = e & 7;
        int kidx = t * 64 + key;
        int kr = kidx / 40, kc2 = kidx - kr * 40;
        float2 f = *(const float2*)&g_K[(base + (bi * 40 + kr) * WW + bj * 40 + kc2) * HD + 2 * dp];
        Kdst[e] = bf16x2(f.x, f.y);
    }
    for (int e = tid; e < 512; e += 256) {
        int d = e >> 5, k2 = e & 31;
        int kidx = t * 64 + 2 * k2;            // even -> pair never crosses a row of 40
        int kr = kidx / 40, kc2 = kidx - kr * 40;
        size_t tok = base + (bi * 40 + kr) * WW + bj * 40 + kc2;
        float lo = g_V[tok * HD + d];
        float hi = g_V[(tok + 1) * HD + d];
        Vdst[e] = bf16x2(lo, hi);
    }
}

// ---------------- attention for p in {4,8} (R8-validated) ----------------
template <int P, int HPC, bool ACCUM>
__global__ __launch_bounds__(P * P * HPC) void attn_small_kernel(
    const float* __restrict__ relw, const float* __restrict__ relh) {
    constexpr int N = P * P;
    constexpr int THREADS = N * HPC;
    constexpr int NBW = WW / P;
    constexpr int NB = NBW * NBW;
    constexpr int HG = NHEADS / HPC;
    __shared__ float Ks[HPC][N][16];
    __shared__ float Vs[HPC][N][16];
    __shared__ float Vc[HPC][P][16];
    __shared__ float Vr[HPC][P][16];
    __shared__ float rwT[16][2 * P];
    __shared__ float rhT[16][2 * P];

    const int cta = blockIdx.x;
    const int hg = cta % HG;
    const int blk = (cta / HG) % NB;
    const int b = cta / (HG * NB);
    const int bi = blk / NBW, bj = blk % NBW;
    const int tid = threadIdx.x;
    const int hh = tid / N;
    const int qi = tid - hh * N;
    const int h = hg * HPC + hh;

    for (int e = tid; e < (2 * P - 1) * 16; e += THREADS) {
        int rr = e >> 4, d = e & 15;
        rwT[d][rr] = relw[e];
        rhT[d][rr] = relh[e];
    }
    for (int e = tid; e < HPC * N * 4; e += THREADS) {
        int hl = e / (N * 4);
        int rem = e - hl * (N * 4);
        int key = rem >> 2, part = (rem & 3) << 2;
        int kr = key / P, kc = key - kr * P;
        int ktok = (bi * P + kr) * WW + bj * P + kc;
        size_t basek = (size_t)(b * NHEADS + hg * HPC + hl) * NTOK;
        *(float4*)&Ks[hl][key][part] = *(const float4*)&g_K[(basek + ktok) * HD + part];
        *(float4*)&Vs[hl][key][part] = *(const float4*)&g_V[(basek + ktok) * HD + part];
    }
    __syncthreads();
    for (int e = tid; e < HPC * P * 16; e += THREADS) {
        int hl = e / (P * 16);
        int rem = e - hl * (P * 16);
        int idx = rem >> 4, dd = rem & 15;
        float sc = 0.f, sr = 0.f;
#pragma unroll
        for (int k2 = 0; k2 < P; k2++) {
            sc += Vs[hl][k2 * P + idx][dd];
            sr += Vs[hl][idx * P + k2][dd];
        }
        Vc[hl][idx][dd] = sc;
        Vr[hl][idx][dd] = sr;
    }
    __syncthreads();

    const int r = qi / P, c = qi - (qi / P) * P;
    const int qtok = (bi * P + r) * WW + bj * P + c;
    const size_t base = (size_t)(b * NHEADS + h) * NTOK;
    float q[16];
    load16(&g_Q[(base + qtok) * HD], q);
    float o[16];
#pragma unroll
    for (int d = 0; d < 16; d++) o[d] = 0.f;
    float ssum = 0.f;

    for (int kk = 0; kk < N; kk++) {
        float kv[16];
        load16(&Ks[hh][kk][0], kv);
        float s = 0.f;
#pragma unroll
        for (int d = 0; d < 16; d++) s = fmaf(q[d], kv[d], s);
        float ew = __expf(s * ATTN_SCALE);
        ssum += ew;
        float vv[16];
        load16(&Vs[hh][kk][0], vv);
#pragma unroll
        for (int d = 0; d < 16; d++) o[d] = fmaf(ew, vv[d], o[d]);
    }
    float inv = 1.f / ssum;
#pragma unroll
    for (int d = 0; d < 16; d++) o[d] *= inv;

    const int cw = P - 1 - c, rw = P - 1 - r;
#pragma unroll 2
    for (int kc = 0; kc < P; kc++) {
        float w = 0.f, wh = 0.f;
#pragma unroll
        for (int d = 0; d < 16; d++) {
            w = fmaf(q[d], rwT[d][kc + cw], w);
            wh = fmaf(q[d], rhT[d][kc + rw], wh);
        }
        float vcv[16], vrv[16];
        load16(&Vc[hh][kc][0], vcv);
        load16(&Vr[hh][kc][0], vrv);
#pragma unroll
        for (int d = 0; d < 16; d++) {
            o[d] = fmaf(w, vcv[d], o[d]);
            o[d] = fmaf(wh, vrv[d], o[d]);
        }
    }
    const int dtok = (bi * NBW + bj) * N + qi;
    float* dst = g_Osum + ((size_t)b * NTOK + dtok) * 128 + h * HD;
#pragma unroll
    for (int d4 = 0; d4 < 4; d4++) {
        float4 val = make_float4(o[4 * d4], o[4 * d4 + 1], o[4 * d4 + 2], o[4 * d4 + 3]);
        if (ACCUM) {
            float4 cur = *(float4*)&dst[4 * d4];
            val.x += cur.x; val.y += cur.y; val.z += cur.z; val.w += cur.w;
        }
        *(float4*)&dst[4 * d4] = val;
    }
}

// ---------------- attention for p=40: bf16 mma + prepacked tiles + double buffer ----------------
__global__ __launch_bounds__(320, 2) void attn40_kernel(
    const float* __restrict__ relw, const float* __restrict__ relh) {
    __shared__ __align__(16) uint32_t KsU[2][512];
    __shared__ __align__(16) uint32_t VtU[2][16 * 36];
    __shared__ float Os[160][17];
    __shared__ float rw[79 * 16], rh[79 * 16];
    __shared__ float Vc[40][16], Vr[40][16];

    const int bh = blockIdx.x / 10;
    const int qc = blockIdx.x - bh * 10;
    const int b = bh >> 5, blk = (bh >> 3) & 3, h = bh & 7;
    const int bi = blk >> 1, bj = blk & 1;
    const int tid = threadIdx.x;
    const size_t base = (size_t)(b * NHEADS + h) * NTOK;

    for (int e = tid; e < 79 * 16; e += 320) { rw[e] = relw[e]; rh[e] = relh[e]; }
    for (int e = tid; e < 640; e += 320) {
        ((float*)Vc)[e] = g_Vc40[bh * 640 + e];
        ((float*)Vr)[e] = g_Vr40[bh * 640 + e];
    }

    const int wid = tid >> 5, lane = tid & 31;
    const int lr = lane >> 2, lc = lane & 3;
    uint32_t qa0, qa1, qa2, qa3;
    {
        int qia = qc * 160 + wid * 16 + lr;
        int qib = qia + 8;
        int ra = qia / 40, ca = qia - ra * 40;
        int rb = qib / 40, cb = qib - rb * 40;
        const float* qpa = &g_Q[(base + (bi * 40 + ra) * WW + bj * 40 + ca) * HD];
        const float* qpb = &g_Q[(base + (bi * 40 + rb) * WW + bj * 40 + cb) * HD];
        float2 f;
        f = *(const float2*)&qpa[2 * lc];     qa0 = bf16x2(f.x * QK_SCALE, f.y * QK_SCALE);
        f = *(const float2*)&qpb[2 * lc];     qa1 = bf16x2(f.x * QK_SCALE, f.y * QK_SCALE);
        f = *(const float2*)&qpa[2 * lc + 8]; qa2 = bf16x2(f.x * QK_SCALE, f.y * QK_SCALE);
        f = *(const float2*)&qpb[2 * lc + 8]; qa3 = bf16x2(f.x * QK_SCALE, f.y * QK_SCALE);
    }
    float oc0[4] = {0.f, 0.f, 0.f, 0.f};
    float oc1[4] = {0.f, 0.f, 0.f, 0.f};
    float rsum0 = 0.f, rsum1 = 0.f;

    const uint32_t* Kp = &g_Kp[(size_t)bh * 25 * 512];
    const uint32_t* Vp = &g_Vtp[(size_t)bh * 25 * 512];
    const int j4 = (tid & 127) << 2;

    uint4 pk, pv;
    // preload + store tile 0
    if (tid < 128) {
        pk = *(const uint4*)&Kp[j4];
        *(uint4*)&KsU[0][j4] = pk;
    } else if (tid < 256) {
        pv = *(const uint4*)&Vp[j4];
        int d = j4 >> 5, k2 = j4 & 31;
        *(uint4*)&VtU[0][d * 36 + k2] = pv;
    }

    for (int t = 0; t < 25; t++) {
        // prefetch tile t+1 (LDG overlapped with this tile's compute)
        if (t < 24) {
            if (tid < 128)      pk = *(const uint4*)&Kp[(t + 1) * 512 + j4];
            else if (tid < 256) pv = *(const uint4*)&Vp[(t + 1) * 512 + j4];
        }
        __syncthreads();            // tile t fully in smem
        const int cb = t & 1;

        uint32_t p[8][2];
#pragma unroll
        for (int g = 0; g < 8; g++) {
            float c0 = 0.f, c1 = 0.f, c2 = 0.f, c3 = 0.f;
            uint32_t kb0 = KsU[cb][(8 * g + lr) * 8 + lc];
            uint32_t kb1 = KsU[cb][(8 * g + lr) * 8 + lc + 4];
            mma_bf16(c0, c1, c2, c3, qa0, qa1, qa2, qa3, kb0, kb1);
            float e0 = ex2f(c0), e1 = ex2f(c1), e2 = ex2f(c2), e3 = ex2f(c3);
            rsum0 += e0 + e1;
            rsum1 += e2 + e3;
            p[g][0] = bf16x2(e0, e1);
            p[g][1] = bf16x2(e2, e3);
        }
#pragma unroll
        for (int gp = 0; gp < 4; gp++) {
            uint32_t a0 = p[2 * gp][0], a1 = p[2 * gp][1];
            uint32_t a2 = p[2 * gp + 1][0], a3 = p[2 * gp + 1][1];
            uint32_t vb0 = VtU[cb][lr * 36 + 8 * gp + lc];
            uint32_t vb1 = VtU[cb][lr * 36 + 8 * gp + lc + 4];
            mma_bf16(oc0[0], oc0[1], oc0[2], oc0[3], a0, a1, a2, a3, vb0, vb1);
            vb0 = VtU[cb][(8 + lr) * 36 + 8 * gp + lc];
            vb1 = VtU[cb][(8 + lr) * 36 + 8 * gp + lc + 4];
            mma_bf16(oc1[0], oc1[1], oc1[2], oc1[3], a0, a1, a2, a3, vb0, vb1);
        }
        // store tile t+1 into the other buffer (nobody reads it now)
        if (t < 24) {
            const int nb = (t + 1) & 1;
            if (tid < 128) {
                *(uint4*)&KsU[nb][j4] = pk;
            } else if (tid < 256) {
                int d = j4 >> 5, k2 = j4 & 31;
                *(uint4*)&VtU[nb][d * 36 + k2] = pv;
            }
        }
    }
    rsum0 += __shfl_xor_sync(0xffffffffu, rsum0, 1);
    rsum0 += __shfl_xor_sync(0xffffffffu, rsum0, 2);
    rsum1 += __shfl_xor_sync(0xffffffffu, rsum1, 1);
    rsum1 += __shfl_xor_sync(0xffffffffu, rsum1, 2);
    float inv0 = 1.f / rsum0, inv1 = 1.f / rsum1;
    {
        int ql = wid * 16;
        Os[ql + lr][2 * lc]         = oc0[0] * inv0;
        Os[ql + lr][2 * lc + 1]     = oc0[1] * inv0;
        Os[ql + lr + 8][2 * lc]     = oc0[2] * inv1;
        Os[ql + lr + 8][2 * lc + 1] = oc0[3] * inv1;
        Os[ql + lr][2 * lc + 8]     = oc1[0] * inv0;
        Os[ql + lr][2 * lc + 9]     = oc1[1] * inv0;
        Os[ql + lr + 8][2 * lc + 8] = oc1[2] * inv1;
        Os[ql + lr + 8][2 * lc + 9] = oc1[3] * inv1;
    }
    __syncthreads();

    // fp32 rel-pos epilogue: 2 threads per query
    const int qloc = tid >> 1, half = tid & 1;
    const int qi = qc * 160 + qloc;
    const int r = qi / 40, c = qi - r * 40;
    float q[16];
    load16(&g_Q[(base + (bi * 40 + r) * WW + bj * 40 + c) * HD], q);
    float o[8] = {0.f, 0.f, 0.f, 0.f, 0.f, 0.f, 0.f, 0.f};
    const int off = half ? (39 - r) : (39 - c);
    const float* tbl = half ? rh : rw;
#pragma unroll 2
    for (int kc = 0; kc < 40; kc++) {
        const float* tp = &tbl[(kc + off) * 16];
        float mine = 0.f;
#pragma unroll
        for (int d = 0; d < 16; d++) mine = fmaf(q[d], tp[d], mine);
        float other = __shfl_xor_sync(0xffffffffu, mine, 1);
        float w  = half ? other : mine;
        float wh = half ? mine  : other;
#pragma unroll
        for (int j = 0; j < 8; j++)
            o[j] = fmaf(w, Vc[kc][half * 8 + j], fmaf(wh, Vr[kc][half * 8 + j], o[j]));
    }
    const int pbase = (bi * 2 + bj) * 1600;
    float* dst = &g_Osum[((size_t)b * NTOK + pbase + qi) * 128 + h * HD + half * 8];
#pragma unroll
    for (int j4b = 0; j4b < 2; j4b++) {
        float4 cur = *(float4*)&dst[4 * j4b];
        cur.x += o[4 * j4b + 0] + Os[qloc][half * 8 + 4 * j4b + 0];
        cur.y += o[4 * j4b + 1] + Os[qloc][half * 8 + 4 * j4b + 1];
        cur.z += o[4 * j4b + 2] + Os[qloc][half * 8 + 4 * j4b + 2];
        cur.w += o[4 * j4b + 3] + Os[qloc][half * 8 + 4 * j4b + 3];
        *(float4*)&dst[4 * j4b] = cur;
    }
}

// ---------------- final via bf16x3 mma: out = Osum @ Wc + bc ----------------
__global__ __launch_bounds__(256) void final_mma_kernel(float* __restrict__ out) {
    __shared__ uint32_t AsH[128][9], AsL[128][9];
    __shared__ uint32_t BsH[64][9], BsL[64][9];
    const int m0 = blockIdx.x * 128;
    const int n0 = blockIdx.y * 64;
    const int tid = threadIdx.x;
    const int wid = tid >> 5, lane = tid & 31;
    const int lr = lane >> 2, lc = lane & 3;
    float c[8][4];
#pragma unroll
    for (int j = 0; j < 8; j++)
#pragma unroll
        for (int i = 0; i < 4; i++) c[j][i] = 0.f;

    for (int kc = 0; kc < 8; kc++) {
        __syncthreads();
        {
            int row = tid >> 1, hf = tid & 1;
            const float* src = &g_Osum[(size_t)(m0 + row) * 128 + kc * 16 + hf * 8];
            float4 f0 = *(const float4*)src;
            float4 f1 = *(const float4*)(src + 4);
            uint32_t h, l;
            split_pair(f0.x, f0.y, h, l); AsH[row][hf * 4 + 0] = h; AsL[row][hf * 4 + 0] = l;
            split_pair(f0.z, f0.w, h, l); AsH[row][hf * 4 + 1] = h; AsL[row][hf * 4 + 1] = l;
            split_pair(f1.x, f1.y, h, l); AsH[row][hf * 4 + 2] = h; AsL[row][hf * 4 + 2] = l;
            split_pair(f1.z, f1.w, h, l); AsH[row][hf * 4 + 3] = h; AsL[row][hf * 4 + 3] = l;
        }
#pragma unroll
        for (int ee = 0; ee < 2; ee++) {
            int e = tid + ee * 256;
            int n = e & 63, kp = e >> 6;
            float b0 = g_Wc[(size_t)(kc * 16 + 2 * kp) * 128 + n0 + n];
            float b1 = g_Wc[(size_t)(kc * 16 + 2 * kp + 1) * 128 + n0 + n];
            uint32_t h, l; split_pair(b0, b1, h, l);
            BsH[n][kp] = h; BsL[n][kp] = l;
        }
        __syncthreads();
        const int rbase = wid * 16;
        uint32_t aH0 = AsH[rbase + lr][lc],     aH1 = AsH[rbase + lr + 8][lc];
        uint32_t aH2 = AsH[rbase + lr][lc + 4], aH3 = AsH[rbase + lr + 8][lc + 4];
        uint32_t aL0 = AsL[rbase + lr][lc],     aL1 = AsL[rbase + lr + 8][lc];
        uint32_t aL2 = AsL[rbase + lr][lc + 4], aL3 = AsL[rbase + lr + 8][lc + 4];
#pragma unroll
        for (int j = 0; j < 8; j++) {
            uint32_t bH0 = BsH[8 * j + lr][lc], bH1 = BsH[8 * j + lr][lc + 4];
            uint32_t bL0 = BsL[8 * j + lr][lc], bL1 = BsL[8 * j + lr][lc + 4];
            mma_bf16(c[j][0], c[j][1], c[j][2], c[j][3], aH0, aH1, aH2, aH3, bH0, bH1);
            mma_bf16(c[j][0], c[j][1], c[j][2], c[j][3], aL0, aL1, aL2, aL3, bH0, bH1);
            mma_bf16(c[j][0], c[j][1], c[j][2], c[j][3], aH0, aH1, aH2, aH3, bL0, bL1);
        }
    }
#pragma unroll
    for (int j = 0; j < 8; j++) {
        int ncol = n0 + 8 * j + 2 * lc;
        float b0v = g_bc[ncol], b1v = g_bc[ncol + 1];
        int t0 = m0 + wid * 16 + lr;
        *(float2*)&out[(size_t)t0 * 128 + ncol] = make_float2(c[j][0] + b0v, c[j][1] + b1v);
        *(float2*)&out[(size_t)(t0 + 8) * 128 + ncol] = make_float2(c[j][2] + b0v, c[j][3] + b1v);
    }
}

// ---------------- launcher ----------------
extern "C" void kernel_launch(void* const* d_in, const int* in_sizes, int n_in,
                              void* d_out, int out_size) {
    (void)in_sizes; (void)n_in; (void)out_size;
    const float* x      = (const float*)d_in[0];
    const float* wq     = (const float*)d_in[1];
    const float* wkv    = (const float*)d_in[2];
    const float* wproj  = (const float*)d_in[3];
    const float* bproj  = (const float*)d_in[4];
    const float* wfinal = (const float*)d_in[5];
    const float* bfinal = (const float*)d_in[6];
    const float* rw0 = (const float*)d_in[7];
    const float* rh0 = (const float*)d_in[8];
    const float* rw1 = (const float*)d_in[9];
    const float* rh1 = (const float*)d_in[10];
    const float* rw2 = (const float*)d_in[11];
    const float* rh2 = (const float*)d_in[12];
    float* out = (float*)d_out;

    qkv_mma_kernel<<<dim3(100, 6), 256>>>(x, wq, wkv);
    wc_kernel<<<128, 128>>>(wproj, wfinal, bproj, bfinal);
    vsum40_kernel<<<64, 640>>>();
    pack40_kernel<<<1600, 256>>>();
    attn_small_kernel<4, 8, false><<<800, 128>>>(rw0, rh0);
    attn_small_kernel<8, 2, true><<<800, 128>>>(rw1, rh1);
    attn40_kernel<<<640, 320>>>(rw2, rh2);
    final_mma_kernel<<<dim3(100, 2), 256>>>(out);
}